// round 10
// baseline (speedup 1.0000x reference)
#include <cuda_runtime.h>

#define TSTEPS 7
typedef unsigned long long u64;

// ---- constant image layout: u64 entries, each a duplicated (w,w) f32 pair ----
enum {
  CW_WI0 = 0,    // 4  Wih_up[:,0]
  CW_WI1 = 4,    // 4  Wih_up[:,1]
  CW_BU  = 8,    // 4  bih_up+bhh_up
  CW_WHU = 12,   // 16 Whh_up
  CW_W1  = 28,   // 32 W1
  CW_B1  = 60,   // 4  b1
  CW_W2  = 64,   // 16 W2
  CW_B2  = 80,   // 4  b2
  CW_WID = 84,   // 16 Wih_dn
  CW_WHD = 100,  // 16 Whh_dn
  CW_BD  = 116,  // 4  bih_dn+bhh_dn
  CW_WO  = 120,  // 4  Wo[0:4]
  CW_WOJ = 124,  // 1  Wo[4]
  CW_BO  = 125,  // 1  bo
  CW_N   = 126
};

__constant__ u64 cw[CW_N];
__device__ u64 g_prep[CW_N];

__device__ __forceinline__ u64 dup_dev(float v) {
    unsigned u = __float_as_uint(v);
    return ((u64)u << 32) | (u64)u;
}

// one thread per constant entry — ~0.5us instead of serialized single-thread prep
__global__ void prep_kernel(const float* Wih_up, const float* Whh_up,
                            const float* bih_up, const float* bhh_up,
                            const float* W1, const float* b1,
                            const float* W2, const float* b2,
                            const float* Wih_dn, const float* Whh_dn,
                            const float* bih_dn, const float* bhh_dn,
                            const float* Wo, const float* bo)
{
    int i = threadIdx.x;
    if (i >= CW_N) return;
    float v;
    if      (i < CW_WI1)  v = Wih_up[2*(i - CW_WI0)];
    else if (i < CW_BU)   v = Wih_up[2*(i - CW_WI1) + 1];
    else if (i < CW_WHU)  v = bih_up[i - CW_BU] + bhh_up[i - CW_BU];
    else if (i < CW_W1)   v = Whh_up[i - CW_WHU];
    else if (i < CW_B1)   v = W1[i - CW_W1];
    else if (i < CW_W2)   v = b1[i - CW_B1];
    else if (i < CW_B2)   v = W2[i - CW_W2];
    else if (i < CW_WID)  v = b2[i - CW_B2];
    else if (i < CW_WHD)  v = Wih_dn[i - CW_WID];
    else if (i < CW_BD)   v = Whh_dn[i - CW_WHD];
    else if (i < CW_WO)   v = bih_dn[i - CW_BD] + bhh_dn[i - CW_BD];
    else if (i < CW_WOJ)  v = Wo[i - CW_WO];
    else if (i == CW_WOJ) v = Wo[4];
    else                  v = bo[0];
    g_prep[i] = dup_dev(v);
}

// ---- f32x2 packed helpers ----
__device__ __forceinline__ u64 pack2(float lo, float hi) {
    u64 r; asm("mov.b64 %0, {%1, %2};" : "=l"(r) : "f"(lo), "f"(hi)); return r;
}
__device__ __forceinline__ void unpack2(u64 p, float& lo, float& hi) {
    asm("mov.b64 {%0, %1}, %2;" : "=f"(lo), "=f"(hi) : "l"(p));
}
__device__ __forceinline__ u64 fma2(u64 a, u64 b, u64 c) {
    u64 d; asm("fma.rn.f32x2 %0, %1, %2, %3;" : "=l"(d) : "l"(a), "l"(b), "l"(c)); return d;
}
__device__ __forceinline__ float htanh(float x) {
    float r; asm("tanh.approx.f32 %0, %1;" : "=f"(r) : "f"(x)); return r;
}
__device__ __forceinline__ u64 tanh2(u64 p) {
    float lo, hi; unpack2(p, lo, hi);
    return pack2(htanh(lo), htanh(hi));
}

// scalar fallback for tail rows (cold path, raw weights)
__device__ void scalar_row(int row, const float* x,
                           const float* Wih_up, const float* Whh_up,
                           const float* bih_up, const float* bhh_up,
                           const float* W1, const float* b1,
                           const float* W2, const float* b2,
                           const float* Wih_dn, const float* Whh_dn,
                           const float* bih_dn, const float* bhh_dn,
                           const float* Wo, const float* bo, float* out)
{
    float xr[18];
    for (int k = 0; k < 18; k++) xr[k] = x[(size_t)row * 18 + k];
    const float* obs = xr; const float* jj = xr + 4; const float* jjd = xr + 11;
    float h[4] = {0,0,0,0}, hup[TSTEPS][4];
    for (int s = 0; s < TSTEPS; s++) {
        int ti = TSTEPS - 1 - s;
        float pre[4];
        for (int i = 0; i < 4; i++) {
            float p = bih_up[i] + bhh_up[i];
            p = fmaf(Wih_up[i*2+0], jj[ti], p);
            p = fmaf(Wih_up[i*2+1], jjd[ti], p);
            for (int k = 0; k < 4; k++) p = fmaf(Whh_up[i*4+k], h[k], p);
            pre[i] = p;
        }
        for (int i = 0; i < 4; i++) { h[i] = htanh(pre[i]); hup[ti][i] = h[i]; }
    }
    float z[8]; for (int k = 0; k < 4; k++) { z[k] = obs[k]; z[4+k] = h[k]; }
    float h0[4];
    for (int i = 0; i < 4; i++) {
        float p = b1[i];
        for (int k = 0; k < 8; k++) p = fmaf(W1[i*8+k], z[k], p);
        h0[i] = htanh(p);
    }
    for (int i = 0; i < 4; i++) {
        float p = b2[i];
        for (int k = 0; k < 4; k++) p = fmaf(W2[i*4+k], h0[k], p);
        h[i] = htanh(p);
    }
    for (int t = 0; t < TSTEPS; t++) {
        float a = fmaf(Wo[4], jj[t], bo[0]);
        for (int k = 0; k < 4; k++) a = fmaf(Wo[k], h[k], a);
        out[(size_t)row * TSTEPS + t] = a;
        float hn[4];
        for (int i = 0; i < 4; i++) {
            float p = bih_dn[i] + bhh_dn[i];
            for (int k = 0; k < 4; k++) {
                p = fmaf(Wih_dn[i*4+k], hup[t][k], p);
                p = fmaf(Whh_dn[i*4+k], h[k], p);
            }
            hn[i] = htanh(p);
        }
        for (int i = 0; i < 4; i++) h[i] = hn[i];
    }
}

__global__ __launch_bounds__(128, 6)
void rec_policy_kernel(const float* __restrict__ x, float* __restrict__ out, int B,
                       const float* Wih_up, const float* Whh_up,
                       const float* bih_up, const float* bhh_up,
                       const float* W1, const float* b1,
                       const float* W2, const float* b2,
                       const float* Wih_dn, const float* Whh_dn,
                       const float* bih_dn, const float* bhh_dn,
                       const float* Wo, const float* bo)
{
    // Per-warp region [32 slots][32 lanes] u64 (8192B):
    //   slots 0..27  hup history (x-gather stage overlays 0..17 transiently;
    //                 acts[t] parks in slot t*4 during the down phase)
    //   slots 28..31 obs park (read once, in the MLP)
    __shared__ u64 sm[4 * 32 * 32];

    const int tid  = threadIdx.x;
    const int lane = tid & 31;
    const int wid  = tid >> 5;
    u64* wsm = sm + wid * (32 * 32);
    const int warpBase = (blockIdx.x * 128 + wid * 32) * 2;
    const int r0 = warpBase + lane * 2;

    const bool fast = (warpBase + 64 <= B);
    if (!fast) {
        if (r0 < B)     scalar_row(r0,   x, Wih_up, Whh_up, bih_up, bhh_up, W1, b1,
                                   W2, b2, Wih_dn, Whh_dn, bih_dn, bhh_dn, Wo, bo, out);
        if (r0 + 1 < B) scalar_row(r0+1, x, Wih_up, Whh_up, bih_up, bhh_up, W1, b1,
                                   W2, b2, Wih_dn, Whh_dn, bih_dn, bhh_dn, Wo, bo, out);
        return;
    }

    // ---- coalesced x gather into the overlay stage (slots 0..17) ----
    {
        const float4* g  = reinterpret_cast<const float4*>(x + (size_t)warpBase * 18);
        float4*       s4 = reinterpret_cast<float4*>(wsm);
        #pragma unroll
        for (int r = 0; r < 9; r++) s4[r * 32 + lane] = g[r * 32 + lane];
    }
    __syncwarp();

    // ---- read own 36 floats; jj+jjd stay in registers, obs parks in smem ----
    u64 X[14];   // X[0..6] = jj pairs, X[7..13] = jjd pairs
    {
        float xb[36];
        const float4* sp = reinterpret_cast<const float4*>(
            reinterpret_cast<const float*>(wsm) + lane * 36);
        #pragma unroll
        for (int k = 0; k < 9; k++) {
            float4 v = sp[k];
            xb[4*k] = v.x; xb[4*k+1] = v.y; xb[4*k+2] = v.z; xb[4*k+3] = v.w;
        }
        __syncwarp();
        #pragma unroll
        for (int t = 0; t < TSTEPS; t++) {
            X[t]     = pack2(xb[4 + t],  xb[18 + 4 + t]);
            X[7 + t] = pack2(xb[11 + t], xb[18 + 11 + t]);
        }
        #pragma unroll
        for (int i = 0; i < 4; i++)
            wsm[(28 + i) * 32 + lane] = pack2(xb[i], xb[18 + i]);   // obs park
    }

    u64 h[4];
    #pragma unroll
    for (int i = 0; i < 4; i++) h[i] = 0ull;

    // ================= UP PHASE =================
    #pragma unroll
    for (int s = 0; s < TSTEPS; s++) {
        const int ti = TSTEPS - 1 - s;
        u64 jjv = X[ti], jdv = X[7 + ti];
        u64 pre[4];
        #pragma unroll
        for (int i = 0; i < 4; i++) {
            u64 p = fma2(cw[CW_WI0 + i], jjv, cw[CW_BU + i]);
            p = fma2(cw[CW_WI1 + i], jdv, p);
            p = fma2(cw[CW_WHU + 4*i + 0], h[0], p);
            p = fma2(cw[CW_WHU + 4*i + 1], h[1], p);
            p = fma2(cw[CW_WHU + 4*i + 2], h[2], p);
            p = fma2(cw[CW_WHU + 4*i + 3], h[3], p);
            pre[i] = p;
        }
        #pragma unroll
        for (int i = 0; i < 4; i++) {
            h[i] = tanh2(pre[i]);
            wsm[(ti * 4 + i) * 32 + lane] = h[i];
        }
    }

    // ================= MLP PHASE =================
    {
        u64 ob0 = wsm[(28 + 0) * 32 + lane];
        u64 ob1 = wsm[(28 + 1) * 32 + lane];
        u64 ob2 = wsm[(28 + 2) * 32 + lane];
        u64 ob3 = wsm[(28 + 3) * 32 + lane];
        u64 h0[4];
        #pragma unroll
        for (int i = 0; i < 4; i++) {
            u64 p = cw[CW_B1 + i];
            p = fma2(cw[CW_W1 + 8*i + 0], ob0, p);
            p = fma2(cw[CW_W1 + 8*i + 1], ob1, p);
            p = fma2(cw[CW_W1 + 8*i + 2], ob2, p);
            p = fma2(cw[CW_W1 + 8*i + 3], ob3, p);
            p = fma2(cw[CW_W1 + 8*i + 4], h[0], p);
            p = fma2(cw[CW_W1 + 8*i + 5], h[1], p);
            p = fma2(cw[CW_W1 + 8*i + 6], h[2], p);
            p = fma2(cw[CW_W1 + 8*i + 7], h[3], p);
            h0[i] = tanh2(p);
        }
        #pragma unroll
        for (int i = 0; i < 4; i++) {
            u64 p = cw[CW_B2 + i];
            p = fma2(cw[CW_W2 + 4*i + 0], h0[0], p);
            p = fma2(cw[CW_W2 + 4*i + 1], h0[1], p);
            p = fma2(cw[CW_W2 + 4*i + 2], h0[2], p);
            p = fma2(cw[CW_W2 + 4*i + 3], h0[3], p);
            h[i] = tanh2(p);
        }
    }

    // ================= DOWN PHASE =================
    #pragma unroll
    for (int t = 0; t < TSTEPS; t++) {
        u64 hu0 = wsm[(t*4 + 0) * 32 + lane];
        u64 hu1 = wsm[(t*4 + 1) * 32 + lane];
        u64 hu2 = wsm[(t*4 + 2) * 32 + lane];
        u64 hu3 = wsm[(t*4 + 3) * 32 + lane];

        u64 a = fma2(cw[CW_WOJ], X[t], cw[CW_BO]);
        a = fma2(cw[CW_WO + 0], h[0], a);
        a = fma2(cw[CW_WO + 1], h[1], a);
        a = fma2(cw[CW_WO + 2], h[2], a);
        a = fma2(cw[CW_WO + 3], h[3], a);
        wsm[(t*4 + 0) * 32 + lane] = a;      // park acts[t] in the consumed slot

        u64 hn[4];
        #pragma unroll
        for (int i = 0; i < 4; i++) {
            u64 p = cw[CW_BD + i];
            p = fma2(cw[CW_WID + 4*i + 0], hu0, p);
            p = fma2(cw[CW_WID + 4*i + 1], hu1, p);
            p = fma2(cw[CW_WID + 4*i + 2], hu2, p);
            p = fma2(cw[CW_WID + 4*i + 3], hu3, p);
            p = fma2(cw[CW_WHD + 4*i + 0], h[0], p);
            p = fma2(cw[CW_WHD + 4*i + 1], h[1], p);
            p = fma2(cw[CW_WHD + 4*i + 2], h[2], p);
            p = fma2(cw[CW_WHD + 4*i + 3], h[3], p);
            hn[i] = tanh2(p);
        }
        #pragma unroll
        for (int i = 0; i < 4; i++) h[i] = hn[i];
    }

    // ---- output flush: parked acts -> 14 contiguous floats per thread ----
    {
        float a0[TSTEPS], a1[TSTEPS];
        #pragma unroll
        for (int t = 0; t < TSTEPS; t++)
            unpack2(wsm[(t*4 + 0) * 32 + lane], a0[t], a1[t]);
        float2* o = reinterpret_cast<float2*>(out + (size_t)r0 * TSTEPS);
        o[0] = make_float2(a0[0], a0[1]);
        o[1] = make_float2(a0[2], a0[3]);
        o[2] = make_float2(a0[4], a0[5]);
        o[3] = make_float2(a0[6], a1[0]);
        o[4] = make_float2(a1[1], a1[2]);
        o[5] = make_float2(a1[3], a1[4]);
        o[6] = make_float2(a1[5], a1[6]);
    }
}

extern "C" void kernel_launch(void* const* d_in, const int* in_sizes, int n_in,
                              void* d_out, int out_size)
{
    const float* x      = (const float*)d_in[0];
    const float* Wih_up = (const float*)d_in[1];
    const float* Whh_up = (const float*)d_in[2];
    const float* bih_up = (const float*)d_in[3];
    const float* bhh_up = (const float*)d_in[4];
    const float* W1     = (const float*)d_in[5];
    const float* b1     = (const float*)d_in[6];
    const float* W2     = (const float*)d_in[7];
    const float* b2     = (const float*)d_in[8];
    const float* Wih_dn = (const float*)d_in[9];
    const float* Whh_dn = (const float*)d_in[10];
    const float* bih_dn = (const float*)d_in[11];
    const float* bhh_dn = (const float*)d_in[12];
    const float* Wo     = (const float*)d_in[13];
    const float* bo     = (const float*)d_in[14];
    float* out = (float*)d_out;

    int B = in_sizes[0] / 18;

    // node 1: weight preprocessing (parallel, one thread per entry)
    prep_kernel<<<1, 128>>>(Wih_up, Whh_up, bih_up, bhh_up, W1, b1, W2, b2,
                            Wih_dn, Whh_dn, bih_dn, bhh_dn, Wo, bo);
    // node 2: publish to constant bank (D2D memcpy, graph-capturable)
    void* src = nullptr;
    cudaGetSymbolAddress(&src, g_prep);
    cudaMemcpyToSymbolAsync(cw, src, sizeof(u64) * CW_N, 0, cudaMemcpyDeviceToDevice);

    // node 3: main kernel
    int rowsPerBlock = 256;            // 128 threads x 2 rows
    int blocks = (B + rowsPerBlock - 1) / rowsPerBlock;
    rec_policy_kernel<<<blocks, 128>>>(x, out, B,
                                       Wih_up, Whh_up, bih_up, bhh_up, W1, b1,
                                       W2, b2, Wih_dn, Whh_dn, bih_dn, bhh_dn, Wo, bo);
}

// round 11
// speedup vs baseline: 1.2048x; 1.2048x over previous
#include <cuda_runtime.h>

#define TSTEPS 7
typedef unsigned long long u64;

// ---- constant image layout: u64 entries, each a duplicated (w,w) f32 pair ----
enum {
  CW_WI0 = 0,    // 4  Wih_up[:,0]
  CW_WI1 = 4,    // 4  Wih_up[:,1]
  CW_BU  = 8,    // 4  bih_up+bhh_up
  CW_WHU = 12,   // 16 Whh_up
  CW_W1  = 28,   // 32 W1
  CW_B1  = 60,   // 4  b1
  CW_W2  = 64,   // 16 W2
  CW_B2  = 80,   // 4  b2
  CW_WID = 84,   // 16 Wih_dn
  CW_WHD = 100,  // 16 Whh_dn
  CW_BD  = 116,  // 4  bih_dn+bhh_dn
  CW_WO  = 120,  // 4  Wo[0:4]
  CW_WOJ = 124,  // 1  Wo[4]
  CW_BO  = 125,  // 1  bo
  CW_N   = 126
};

__constant__ u64 cw[CW_N];
__device__ u64 g_prep[CW_N];

__device__ __forceinline__ u64 dup_dev(float v) {
    unsigned u = __float_as_uint(v);
    return ((u64)u << 32) | (u64)u;
}

// one thread per constant entry
__global__ void prep_kernel(const float* Wih_up, const float* Whh_up,
                            const float* bih_up, const float* bhh_up,
                            const float* W1, const float* b1,
                            const float* W2, const float* b2,
                            const float* Wih_dn, const float* Whh_dn,
                            const float* bih_dn, const float* bhh_dn,
                            const float* Wo, const float* bo)
{
    int i = threadIdx.x;
    if (i >= CW_N) return;
    float v;
    if      (i < CW_WI1)  v = Wih_up[2*(i - CW_WI0)];
    else if (i < CW_BU)   v = Wih_up[2*(i - CW_WI1) + 1];
    else if (i < CW_WHU)  v = bih_up[i - CW_BU] + bhh_up[i - CW_BU];
    else if (i < CW_W1)   v = Whh_up[i - CW_WHU];
    else if (i < CW_B1)   v = W1[i - CW_W1];
    else if (i < CW_W2)   v = b1[i - CW_B1];
    else if (i < CW_B2)   v = W2[i - CW_W2];
    else if (i < CW_WID)  v = b2[i - CW_B2];
    else if (i < CW_WHD)  v = Wih_dn[i - CW_WID];
    else if (i < CW_BD)   v = Whh_dn[i - CW_WHD];
    else if (i < CW_WO)   v = bih_dn[i - CW_BD] + bhh_dn[i - CW_BD];
    else if (i < CW_WOJ)  v = Wo[i - CW_WO];
    else if (i == CW_WOJ) v = Wo[4];
    else                  v = bo[0];
    g_prep[i] = dup_dev(v);
}

// ---- f32x2 packed helpers ----
__device__ __forceinline__ u64 pack2(float lo, float hi) {
    u64 r; asm("mov.b64 %0, {%1, %2};" : "=l"(r) : "f"(lo), "f"(hi)); return r;
}
__device__ __forceinline__ void unpack2(u64 p, float& lo, float& hi) {
    asm("mov.b64 {%0, %1}, %2;" : "=f"(lo), "=f"(hi) : "l"(p));
}
__device__ __forceinline__ u64 fma2(u64 a, u64 b, u64 c) {
    u64 d; asm("fma.rn.f32x2 %0, %1, %2, %3;" : "=l"(d) : "l"(a), "l"(b), "l"(c)); return d;
}
__device__ __forceinline__ float htanh(float x) {
    float r; asm("tanh.approx.f32 %0, %1;" : "=f"(r) : "f"(x)); return r;
}
__device__ __forceinline__ u64 tanh2(u64 p) {
    float lo, hi; unpack2(p, lo, hi);
    return pack2(htanh(lo), htanh(hi));
}

// scalar fallback for tail rows (cold path, raw weights)
__device__ void scalar_row(int row, const float* x,
                           const float* Wih_up, const float* Whh_up,
                           const float* bih_up, const float* bhh_up,
                           const float* W1, const float* b1,
                           const float* W2, const float* b2,
                           const float* Wih_dn, const float* Whh_dn,
                           const float* bih_dn, const float* bhh_dn,
                           const float* Wo, const float* bo, float* out)
{
    float xr[18];
    for (int k = 0; k < 18; k++) xr[k] = x[(size_t)row * 18 + k];
    const float* obs = xr; const float* jj = xr + 4; const float* jjd = xr + 11;
    float h[4] = {0,0,0,0}, hup[TSTEPS][4];
    for (int s = 0; s < TSTEPS; s++) {
        int ti = TSTEPS - 1 - s;
        float pre[4];
        for (int i = 0; i < 4; i++) {
            float p = bih_up[i] + bhh_up[i];
            p = fmaf(Wih_up[i*2+0], jj[ti], p);
            p = fmaf(Wih_up[i*2+1], jjd[ti], p);
            for (int k = 0; k < 4; k++) p = fmaf(Whh_up[i*4+k], h[k], p);
            pre[i] = p;
        }
        for (int i = 0; i < 4; i++) { h[i] = htanh(pre[i]); hup[ti][i] = h[i]; }
    }
    float z[8]; for (int k = 0; k < 4; k++) { z[k] = obs[k]; z[4+k] = h[k]; }
    float h0[4];
    for (int i = 0; i < 4; i++) {
        float p = b1[i];
        for (int k = 0; k < 8; k++) p = fmaf(W1[i*8+k], z[k], p);
        h0[i] = htanh(p);
    }
    for (int i = 0; i < 4; i++) {
        float p = b2[i];
        for (int k = 0; k < 4; k++) p = fmaf(W2[i*4+k], h0[k], p);
        h[i] = htanh(p);
    }
    for (int t = 0; t < TSTEPS; t++) {
        float a = fmaf(Wo[4], jj[t], bo[0]);
        for (int k = 0; k < 4; k++) a = fmaf(Wo[k], h[k], a);
        out[(size_t)row * TSTEPS + t] = a;
        float hn[4];
        for (int i = 0; i < 4; i++) {
            float p = bih_dn[i] + bhh_dn[i];
            for (int k = 0; k < 4; k++) {
                p = fmaf(Wih_dn[i*4+k], hup[t][k], p);
                p = fmaf(Whh_dn[i*4+k], h[k], p);
            }
            hn[i] = htanh(p);
        }
        for (int i = 0; i < 4; i++) h[i] = hn[i];
    }
}

__global__ __launch_bounds__(128, 5)
void rec_policy_kernel(const float* __restrict__ x, float* __restrict__ out, int B,
                       const float* Wih_up, const float* Whh_up,
                       const float* bih_up, const float* bhh_up,
                       const float* W1, const float* b1,
                       const float* W2, const float* b2,
                       const float* Wih_dn, const float* Whh_dn,
                       const float* bih_dn, const float* bhh_dn,
                       const float* Wo, const float* bo)
{
    // Per-warp region [28 slots][32 lanes] u64 (7168B). The transient x-gather stage
    // (4608B = slots 0..17) overlays the hup slots: it is fully consumed into regs
    // (with a __syncwarp) before the first hup write. acts[t] parks in slot t*4
    // during the down phase after that slot's hup value is consumed.
    __shared__ u64 sm[4 * 28 * 32];

    const int tid  = threadIdx.x;
    const int lane = tid & 31;
    const int wid  = tid >> 5;
    u64* wsm = sm + wid * (28 * 32);
    const int warpBase = (blockIdx.x * 128 + wid * 32) * 2;
    const int r0 = warpBase + lane * 2;

    const bool fast = (warpBase + 64 <= B);
    if (!fast) {
        if (r0 < B)     scalar_row(r0,   x, Wih_up, Whh_up, bih_up, bhh_up, W1, b1,
                                   W2, b2, Wih_dn, Whh_dn, bih_dn, bhh_dn, Wo, bo, out);
        if (r0 + 1 < B) scalar_row(r0+1, x, Wih_up, Whh_up, bih_up, bhh_up, W1, b1,
                                   W2, b2, Wih_dn, Whh_dn, bih_dn, bhh_dn, Wo, bo, out);
        return;
    }

    // ---- coalesced x gather into the overlay stage (slots 0..17) ----
    {
        const float4* g  = reinterpret_cast<const float4*>(x + (size_t)warpBase * 18);
        float4*       s4 = reinterpret_cast<float4*>(wsm);
        #pragma unroll
        for (int r = 0; r < 9; r++) s4[r * 32 + lane] = g[r * 32 + lane];
    }
    __syncwarp();

    // ---- read own 36 floats, pack row-pair X[18] (stays in registers) ----
    u64 X[18];
    {
        float xb[36];
        const float4* sp = reinterpret_cast<const float4*>(
            reinterpret_cast<const float*>(wsm) + lane * 36);
        #pragma unroll
        for (int k = 0; k < 9; k++) {
            float4 v = sp[k];
            xb[4*k] = v.x; xb[4*k+1] = v.y; xb[4*k+2] = v.z; xb[4*k+3] = v.w;
        }
        __syncwarp();
        #pragma unroll
        for (int j = 0; j < 18; j++) X[j] = pack2(xb[j], xb[18 + j]);
    }

    u64 h[4];
    #pragma unroll
    for (int i = 0; i < 4; i++) h[i] = 0ull;

    // ================= UP PHASE =================
    #pragma unroll
    for (int s = 0; s < TSTEPS; s++) {
        const int ti = TSTEPS - 1 - s;
        u64 jjv = X[4 + ti], jdv = X[11 + ti];
        u64 pre[4];
        #pragma unroll
        for (int i = 0; i < 4; i++) {
            u64 p = fma2(cw[CW_WI0 + i], jjv, cw[CW_BU + i]);
            p = fma2(cw[CW_WI1 + i], jdv, p);
            p = fma2(cw[CW_WHU + 4*i + 0], h[0], p);
            p = fma2(cw[CW_WHU + 4*i + 1], h[1], p);
            p = fma2(cw[CW_WHU + 4*i + 2], h[2], p);
            p = fma2(cw[CW_WHU + 4*i + 3], h[3], p);
            pre[i] = p;
        }
        #pragma unroll
        for (int i = 0; i < 4; i++) {
            h[i] = tanh2(pre[i]);
            wsm[(ti * 4 + i) * 32 + lane] = h[i];
        }
    }

    // ================= MLP PHASE =================
    {
        u64 h0[4];
        #pragma unroll
        for (int i = 0; i < 4; i++) {
            u64 p = cw[CW_B1 + i];
            p = fma2(cw[CW_W1 + 8*i + 0], X[0], p);
            p = fma2(cw[CW_W1 + 8*i + 1], X[1], p);
            p = fma2(cw[CW_W1 + 8*i + 2], X[2], p);
            p = fma2(cw[CW_W1 + 8*i + 3], X[3], p);
            p = fma2(cw[CW_W1 + 8*i + 4], h[0], p);
            p = fma2(cw[CW_W1 + 8*i + 5], h[1], p);
            p = fma2(cw[CW_W1 + 8*i + 6], h[2], p);
            p = fma2(cw[CW_W1 + 8*i + 7], h[3], p);
            h0[i] = tanh2(p);
        }
        #pragma unroll
        for (int i = 0; i < 4; i++) {
            u64 p = cw[CW_B2 + i];
            p = fma2(cw[CW_W2 + 4*i + 0], h0[0], p);
            p = fma2(cw[CW_W2 + 4*i + 1], h0[1], p);
            p = fma2(cw[CW_W2 + 4*i + 2], h0[2], p);
            p = fma2(cw[CW_W2 + 4*i + 3], h0[3], p);
            h[i] = tanh2(p);
        }
    }

    // ================= DOWN PHASE =================
    #pragma unroll
    for (int t = 0; t < TSTEPS; t++) {
        u64 hu0 = wsm[(t*4 + 0) * 32 + lane];
        u64 hu1 = wsm[(t*4 + 1) * 32 + lane];
        u64 hu2 = wsm[(t*4 + 2) * 32 + lane];
        u64 hu3 = wsm[(t*4 + 3) * 32 + lane];

        u64 a = fma2(cw[CW_WOJ], X[4 + t], cw[CW_BO]);
        a = fma2(cw[CW_WO + 0], h[0], a);
        a = fma2(cw[CW_WO + 1], h[1], a);
        a = fma2(cw[CW_WO + 2], h[2], a);
        a = fma2(cw[CW_WO + 3], h[3], a);
        wsm[(t*4 + 0) * 32 + lane] = a;      // park acts[t] in the consumed slot

        u64 hn[4];
        #pragma unroll
        for (int i = 0; i < 4; i++) {
            u64 p = cw[CW_BD + i];
            p = fma2(cw[CW_WID + 4*i + 0], hu0, p);
            p = fma2(cw[CW_WID + 4*i + 1], hu1, p);
            p = fma2(cw[CW_WID + 4*i + 2], hu2, p);
            p = fma2(cw[CW_WID + 4*i + 3], hu3, p);
            p = fma2(cw[CW_WHD + 4*i + 0], h[0], p);
            p = fma2(cw[CW_WHD + 4*i + 1], h[1], p);
            p = fma2(cw[CW_WHD + 4*i + 2], h[2], p);
            p = fma2(cw[CW_WHD + 4*i + 3], h[3], p);
            hn[i] = tanh2(p);
        }
        #pragma unroll
        for (int i = 0; i < 4; i++) h[i] = hn[i];
    }

    // ---- output flush: parked acts -> 14 contiguous floats per thread ----
    {
        float a0[TSTEPS], a1[TSTEPS];
        #pragma unroll
        for (int t = 0; t < TSTEPS; t++)
            unpack2(wsm[(t*4 + 0) * 32 + lane], a0[t], a1[t]);
        float2* o = reinterpret_cast<float2*>(out + (size_t)r0 * TSTEPS);
        o[0] = make_float2(a0[0], a0[1]);
        o[1] = make_float2(a0[2], a0[3]);
        o[2] = make_float2(a0[4], a0[5]);
        o[3] = make_float2(a0[6], a1[0]);
        o[4] = make_float2(a1[1], a1[2]);
        o[5] = make_float2(a1[3], a1[4]);
        o[6] = make_float2(a1[5], a1[6]);
    }
}

extern "C" void kernel_launch(void* const* d_in, const int* in_sizes, int n_in,
                              void* d_out, int out_size)
{
    const float* x      = (const float*)d_in[0];
    const float* Wih_up = (const float*)d_in[1];
    const float* Whh_up = (const float*)d_in[2];
    const float* bih_up = (const float*)d_in[3];
    const float* bhh_up = (const float*)d_in[4];
    const float* W1     = (const float*)d_in[5];
    const float* b1     = (const float*)d_in[6];
    const float* W2     = (const float*)d_in[7];
    const float* b2     = (const float*)d_in[8];
    const float* Wih_dn = (const float*)d_in[9];
    const float* Whh_dn = (const float*)d_in[10];
    const float* bih_dn = (const float*)d_in[11];
    const float* bhh_dn = (const float*)d_in[12];
    const float* Wo     = (const float*)d_in[13];
    const float* bo     = (const float*)d_in[14];
    float* out = (float*)d_out;

    int B = in_sizes[0] / 18;

    // node 1: weight preprocessing (parallel, one thread per entry)
    prep_kernel<<<1, 128>>>(Wih_up, Whh_up, bih_up, bhh_up, W1, b1, W2, b2,
                            Wih_dn, Whh_dn, bih_dn, bhh_dn, Wo, bo);
    // node 2: publish to constant bank (D2D memcpy, graph-capturable)
    void* src = nullptr;
    cudaGetSymbolAddress(&src, g_prep);
    cudaMemcpyToSymbolAsync(cw, src, sizeof(u64) * CW_N, 0, cudaMemcpyDeviceToDevice);

    // node 3: main kernel
    int rowsPerBlock = 256;            // 128 threads x 2 rows
    int blocks = (B + rowsPerBlock - 1) / rowsPerBlock;
    rec_policy_kernel<<<blocks, 128>>>(x, out, B,
                                       Wih_up, Whh_up, bih_up, bhh_up, W1, b1,
                                       W2, b2, Wih_dn, Whh_dn, bih_dn, bhh_dn, Wo, bo);
}

// round 12
// speedup vs baseline: 1.2100x; 1.0044x over previous
#include <cuda_runtime.h>

#define TSTEPS 7
typedef unsigned long long u64;

// ---- constant image layout: u64 entries, each a duplicated (w,w) f32 pair ----
enum {
  CW_WI0 = 0,    // 4  Wih_up[:,0]
  CW_WI1 = 4,    // 4  Wih_up[:,1]
  CW_BU  = 8,    // 4  bih_up+bhh_up
  CW_WHU = 12,   // 16 Whh_up
  CW_W1  = 28,   // 32 W1
  CW_B1  = 60,   // 4  b1
  CW_W2  = 64,   // 16 W2
  CW_B2  = 80,   // 4  b2
  CW_WID = 84,   // 16 Wih_dn
  CW_WHD = 100,  // 16 Whh_dn
  CW_BD  = 116,  // 4  bih_dn+bhh_dn
  CW_WO  = 120,  // 4  Wo[0:4]
  CW_WOJ = 124,  // 1  Wo[4]
  CW_BO  = 125,  // 1  bo
  CW_N   = 126
};

__constant__ u64 cw[CW_N];
__device__ u64 g_prep[CW_N];

__device__ __forceinline__ u64 dup_dev(float v) {
    unsigned u = __float_as_uint(v);
    return ((u64)u << 32) | (u64)u;
}

// one thread per constant entry
__global__ void prep_kernel(const float* Wih_up, const float* Whh_up,
                            const float* bih_up, const float* bhh_up,
                            const float* W1, const float* b1,
                            const float* W2, const float* b2,
                            const float* Wih_dn, const float* Whh_dn,
                            const float* bih_dn, const float* bhh_dn,
                            const float* Wo, const float* bo)
{
    int i = threadIdx.x;
    if (i >= CW_N) return;
    float v;
    if      (i < CW_WI1)  v = Wih_up[2*(i - CW_WI0)];
    else if (i < CW_BU)   v = Wih_up[2*(i - CW_WI1) + 1];
    else if (i < CW_WHU)  v = bih_up[i - CW_BU] + bhh_up[i - CW_BU];
    else if (i < CW_W1)   v = Whh_up[i - CW_WHU];
    else if (i < CW_B1)   v = W1[i - CW_W1];
    else if (i < CW_W2)   v = b1[i - CW_B1];
    else if (i < CW_B2)   v = W2[i - CW_W2];
    else if (i < CW_WID)  v = b2[i - CW_B2];
    else if (i < CW_WHD)  v = Wih_dn[i - CW_WID];
    else if (i < CW_BD)   v = Whh_dn[i - CW_WHD];
    else if (i < CW_WO)   v = bih_dn[i - CW_BD] + bhh_dn[i - CW_BD];
    else if (i < CW_WOJ)  v = Wo[i - CW_WO];
    else if (i == CW_WOJ) v = Wo[4];
    else                  v = bo[0];
    g_prep[i] = dup_dev(v);
}

// ---- f32x2 packed helpers ----
__device__ __forceinline__ u64 pack2(float lo, float hi) {
    u64 r; asm("mov.b64 %0, {%1, %2};" : "=l"(r) : "f"(lo), "f"(hi)); return r;
}
__device__ __forceinline__ void unpack2(u64 p, float& lo, float& hi) {
    asm("mov.b64 {%0, %1}, %2;" : "=f"(lo), "=f"(hi) : "l"(p));
}
__device__ __forceinline__ u64 fma2(u64 a, u64 b, u64 c) {
    u64 d; asm("fma.rn.f32x2 %0, %1, %2, %3;" : "=l"(d) : "l"(a), "l"(b), "l"(c)); return d;
}
__device__ __forceinline__ float htanh(float x) {
    float r; asm("tanh.approx.f32 %0, %1;" : "=f"(r) : "f"(x)); return r;
}
__device__ __forceinline__ u64 tanh2(u64 p) {
    float lo, hi; unpack2(p, lo, hi);
    return pack2(htanh(lo), htanh(hi));
}

// scalar fallback for tail rows (cold path, raw weights)
__device__ void scalar_row(int row, const float* x,
                           const float* Wih_up, const float* Whh_up,
                           const float* bih_up, const float* bhh_up,
                           const float* W1, const float* b1,
                           const float* W2, const float* b2,
                           const float* Wih_dn, const float* Whh_dn,
                           const float* bih_dn, const float* bhh_dn,
                           const float* Wo, const float* bo, float* out)
{
    float xr[18];
    for (int k = 0; k < 18; k++) xr[k] = x[(size_t)row * 18 + k];
    const float* obs = xr; const float* jj = xr + 4; const float* jjd = xr + 11;
    float h[4] = {0,0,0,0}, hup[TSTEPS][4];
    for (int s = 0; s < TSTEPS; s++) {
        int ti = TSTEPS - 1 - s;
        float pre[4];
        for (int i = 0; i < 4; i++) {
            float p = bih_up[i] + bhh_up[i];
            p = fmaf(Wih_up[i*2+0], jj[ti], p);
            p = fmaf(Wih_up[i*2+1], jjd[ti], p);
            for (int k = 0; k < 4; k++) p = fmaf(Whh_up[i*4+k], h[k], p);
            pre[i] = p;
        }
        for (int i = 0; i < 4; i++) { h[i] = htanh(pre[i]); hup[ti][i] = h[i]; }
    }
    float z[8]; for (int k = 0; k < 4; k++) { z[k] = obs[k]; z[4+k] = h[k]; }
    float h0[4];
    for (int i = 0; i < 4; i++) {
        float p = b1[i];
        for (int k = 0; k < 8; k++) p = fmaf(W1[i*8+k], z[k], p);
        h0[i] = htanh(p);
    }
    for (int i = 0; i < 4; i++) {
        float p = b2[i];
        for (int k = 0; k < 4; k++) p = fmaf(W2[i*4+k], h0[k], p);
        h[i] = htanh(p);
    }
    for (int t = 0; t < TSTEPS; t++) {
        float a = fmaf(Wo[4], jj[t], bo[0]);
        for (int k = 0; k < 4; k++) a = fmaf(Wo[k], h[k], a);
        out[(size_t)row * TSTEPS + t] = a;
        float hn[4];
        for (int i = 0; i < 4; i++) {
            float p = bih_dn[i] + bhh_dn[i];
            for (int k = 0; k < 4; k++) {
                p = fmaf(Wih_dn[i*4+k], hup[t][k], p);
                p = fmaf(Whh_dn[i*4+k], h[k], p);
            }
            hn[i] = htanh(p);
        }
        for (int i = 0; i < 4; i++) h[i] = hn[i];
    }
}

__global__ __launch_bounds__(128, 5)
void rec_policy_kernel(const float* __restrict__ x, float* __restrict__ out, int B,
                       const float* Wih_up, const float* Whh_up,
                       const float* bih_up, const float* bhh_up,
                       const float* W1, const float* b1,
                       const float* W2, const float* b2,
                       const float* Wih_dn, const float* Whh_dn,
                       const float* bih_dn, const float* bhh_dn,
                       const float* Wo, const float* bo)
{
    // Per-warp region [28 slots][32 lanes] u64 (7168B). The transient x-gather stage
    // (4608B = slots 0..17) overlays the hup slots: it is fully consumed into regs
    // (with a __syncwarp) before the first hup write. acts[t] parks in slot t*4
    // during the down phase after that slot's hup value is consumed.
    __shared__ u64 sm[4 * 28 * 32];

    const int tid  = threadIdx.x;
    const int lane = tid & 31;
    const int wid  = tid >> 5;
    u64* wsm = sm + wid * (28 * 32);
    const int warpBase = (blockIdx.x * 128 + wid * 32) * 2;
    const int r0 = warpBase + lane * 2;

    const bool fast = (warpBase + 64 <= B);
    if (!fast) {
        if (r0 < B)     scalar_row(r0,   x, Wih_up, Whh_up, bih_up, bhh_up, W1, b1,
                                   W2, b2, Wih_dn, Whh_dn, bih_dn, bhh_dn, Wo, bo, out);
        if (r0 + 1 < B) scalar_row(r0+1, x, Wih_up, Whh_up, bih_up, bhh_up, W1, b1,
                                   W2, b2, Wih_dn, Whh_dn, bih_dn, bhh_dn, Wo, bo, out);
        return;
    }

    // ---- coalesced x gather into the overlay stage (slots 0..17) ----
    {
        const float4* g  = reinterpret_cast<const float4*>(x + (size_t)warpBase * 18);
        float4*       s4 = reinterpret_cast<float4*>(wsm);
        #pragma unroll
        for (int r = 0; r < 9; r++) s4[r * 32 + lane] = g[r * 32 + lane];
    }
    __syncwarp();

    // ---- read own 36 floats, pack row-pair X[18] (stays in registers) ----
    u64 X[18];
    {
        float xb[36];
        const float4* sp = reinterpret_cast<const float4*>(
            reinterpret_cast<const float*>(wsm) + lane * 36);
        #pragma unroll
        for (int k = 0; k < 9; k++) {
            float4 v = sp[k];
            xb[4*k] = v.x; xb[4*k+1] = v.y; xb[4*k+2] = v.z; xb[4*k+3] = v.w;
        }
        __syncwarp();
        #pragma unroll
        for (int j = 0; j < 18; j++) X[j] = pack2(xb[j], xb[18 + j]);
    }

    u64 h[4];

    // ================= UP PHASE =================
    // step s=0 (ti=6) specialized: h == 0 so the 16 whu*h fma2s are exact identities.
    {
        const int ti = TSTEPS - 1;
        u64 jjv = X[4 + ti], jdv = X[11 + ti];
        #pragma unroll
        for (int i = 0; i < 4; i++) {
            u64 p = fma2(cw[CW_WI0 + i], jjv, cw[CW_BU + i]);
            p = fma2(cw[CW_WI1 + i], jdv, p);
            h[i] = tanh2(p);
            wsm[(ti * 4 + i) * 32 + lane] = h[i];
        }
    }
    #pragma unroll
    for (int s = 1; s < TSTEPS; s++) {
        const int ti = TSTEPS - 1 - s;
        u64 jjv = X[4 + ti], jdv = X[11 + ti];
        u64 pre[4];
        #pragma unroll
        for (int i = 0; i < 4; i++) {
            u64 p = fma2(cw[CW_WI0 + i], jjv, cw[CW_BU + i]);
            p = fma2(cw[CW_WI1 + i], jdv, p);
            p = fma2(cw[CW_WHU + 4*i + 0], h[0], p);
            p = fma2(cw[CW_WHU + 4*i + 1], h[1], p);
            p = fma2(cw[CW_WHU + 4*i + 2], h[2], p);
            p = fma2(cw[CW_WHU + 4*i + 3], h[3], p);
            pre[i] = p;
        }
        #pragma unroll
        for (int i = 0; i < 4; i++) {
            h[i] = tanh2(pre[i]);
            wsm[(ti * 4 + i) * 32 + lane] = h[i];
        }
    }

    // ================= MLP PHASE =================
    {
        u64 h0[4];
        #pragma unroll
        for (int i = 0; i < 4; i++) {
            u64 p = cw[CW_B1 + i];
            p = fma2(cw[CW_W1 + 8*i + 0], X[0], p);
            p = fma2(cw[CW_W1 + 8*i + 1], X[1], p);
            p = fma2(cw[CW_W1 + 8*i + 2], X[2], p);
            p = fma2(cw[CW_W1 + 8*i + 3], X[3], p);
            p = fma2(cw[CW_W1 + 8*i + 4], h[0], p);
            p = fma2(cw[CW_W1 + 8*i + 5], h[1], p);
            p = fma2(cw[CW_W1 + 8*i + 6], h[2], p);
            p = fma2(cw[CW_W1 + 8*i + 7], h[3], p);
            h0[i] = tanh2(p);
        }
        #pragma unroll
        for (int i = 0; i < 4; i++) {
            u64 p = cw[CW_B2 + i];
            p = fma2(cw[CW_W2 + 4*i + 0], h0[0], p);
            p = fma2(cw[CW_W2 + 4*i + 1], h0[1], p);
            p = fma2(cw[CW_W2 + 4*i + 2], h0[2], p);
            p = fma2(cw[CW_W2 + 4*i + 3], h0[3], p);
            h[i] = tanh2(p);
        }
    }

    // ================= DOWN PHASE =================
    // Last iteration (t=6) computes only acts: the final h_new of the scan is
    // never consumed (only acts are outputs), so its 32 fma2 + 4 tanh2 + 4 LDS
    // are dead work.
    #pragma unroll
    for (int t = 0; t < TSTEPS; t++) {
        u64 a = fma2(cw[CW_WOJ], X[4 + t], cw[CW_BO]);
        a = fma2(cw[CW_WO + 0], h[0], a);
        a = fma2(cw[CW_WO + 1], h[1], a);
        a = fma2(cw[CW_WO + 2], h[2], a);
        a = fma2(cw[CW_WO + 3], h[3], a);

        if (t < TSTEPS - 1) {
            u64 hu0 = wsm[(t*4 + 0) * 32 + lane];
            u64 hu1 = wsm[(t*4 + 1) * 32 + lane];
            u64 hu2 = wsm[(t*4 + 2) * 32 + lane];
            u64 hu3 = wsm[(t*4 + 3) * 32 + lane];
            wsm[(t*4 + 0) * 32 + lane] = a;      // park acts[t] in the consumed slot

            u64 hn[4];
            #pragma unroll
            for (int i = 0; i < 4; i++) {
                u64 p = cw[CW_BD + i];
                p = fma2(cw[CW_WID + 4*i + 0], hu0, p);
                p = fma2(cw[CW_WID + 4*i + 1], hu1, p);
                p = fma2(cw[CW_WID + 4*i + 2], hu2, p);
                p = fma2(cw[CW_WID + 4*i + 3], hu3, p);
                p = fma2(cw[CW_WHD + 4*i + 0], h[0], p);
                p = fma2(cw[CW_WHD + 4*i + 1], h[1], p);
                p = fma2(cw[CW_WHD + 4*i + 2], h[2], p);
                p = fma2(cw[CW_WHD + 4*i + 3], h[3], p);
                hn[i] = tanh2(p);
            }
            #pragma unroll
            for (int i = 0; i < 4; i++) h[i] = hn[i];
        } else {
            wsm[(t*4 + 0) * 32 + lane] = a;      // park acts[6]; no h update needed
        }
    }

    // ---- output flush: parked acts -> 14 contiguous floats per thread ----
    {
        float a0[TSTEPS], a1[TSTEPS];
        #pragma unroll
        for (int t = 0; t < TSTEPS; t++)
            unpack2(wsm[(t*4 + 0) * 32 + lane], a0[t], a1[t]);
        float2* o = reinterpret_cast<float2*>(out + (size_t)r0 * TSTEPS);
        o[0] = make_float2(a0[0], a0[1]);
        o[1] = make_float2(a0[2], a0[3]);
        o[2] = make_float2(a0[4], a0[5]);
        o[3] = make_float2(a0[6], a1[0]);
        o[4] = make_float2(a1[1], a1[2]);
        o[5] = make_float2(a1[3], a1[4]);
        o[6] = make_float2(a1[5], a1[6]);
    }
}

extern "C" void kernel_launch(void* const* d_in, const int* in_sizes, int n_in,
                              void* d_out, int out_size)
{
    const float* x      = (const float*)d_in[0];
    const float* Wih_up = (const float*)d_in[1];
    const float* Whh_up = (const float*)d_in[2];
    const float* bih_up = (const float*)d_in[3];
    const float* bhh_up = (const float*)d_in[4];
    const float* W1     = (const float*)d_in[5];
    const float* b1     = (const float*)d_in[6];
    const float* W2     = (const float*)d_in[7];
    const float* b2     = (const float*)d_in[8];
    const float* Wih_dn = (const float*)d_in[9];
    const float* Whh_dn = (const float*)d_in[10];
    const float* bih_dn = (const float*)d_in[11];
    const float* bhh_dn = (const float*)d_in[12];
    const float* Wo     = (const float*)d_in[13];
    const float* bo     = (const float*)d_in[14];
    float* out = (float*)d_out;

    int B = in_sizes[0] / 18;

    // node 1: weight preprocessing (parallel, one thread per entry)
    prep_kernel<<<1, 128>>>(Wih_up, Whh_up, bih_up, bhh_up, W1, b1, W2, b2,
                            Wih_dn, Whh_dn, bih_dn, bhh_dn, Wo, bo);
    // node 2: publish to constant bank (D2D memcpy, graph-capturable)
    void* src = nullptr;
    cudaGetSymbolAddress(&src, g_prep);
    cudaMemcpyToSymbolAsync(cw, src, sizeof(u64) * CW_N, 0, cudaMemcpyDeviceToDevice);

    // node 3: main kernel
    int rowsPerBlock = 256;            // 128 threads x 2 rows
    int blocks = (B + rowsPerBlock - 1) / rowsPerBlock;
    rec_policy_kernel<<<blocks, 128>>>(x, out, B,
                                       Wih_up, Whh_up, bih_up, bhh_up, W1, b1,
                                       W2, b2, Wih_dn, Whh_dn, bih_dn, bhh_dn, Wo, bo);
}